// round 2
// baseline (speedup 1.0000x reference)
#include <cuda_runtime.h>
#include <cstdint>

// Problem dims
#define TT   512
#define BB   64
#define II   512
#define HH   512
#define G4   2048          // 4*H gate rows
#define NCTA 128           // persistent CTAs (each owns 4 h-indices)

// ---------------------------------------------------------------------------
// Global scratch (static __device__ arrays — no allocation allowed)
// ---------------------------------------------------------------------------
__device__ float g_xp[(size_t)TT * G4 * BB];   // x_proj, layout [t][g][b]   (256 MB)
__device__ float g_h[2][HH * BB];              // h double buffer, layout [j][b]
__device__ unsigned int          g_bar_cnt;
__device__ volatile unsigned int g_bar_gen;

// ---------------------------------------------------------------------------
// PTX helpers
// ---------------------------------------------------------------------------
__device__ __forceinline__ uint32_t smem_u32(const void* p) {
    uint32_t a;
    asm("{ .reg .u64 t; cvta.to.shared.u64 t, %1; cvt.u32.u64 %0, t; }"
        : "=r"(a) : "l"(p));
    return a;
}
__device__ __forceinline__ void mbar_init(uint32_t addr, uint32_t count) {
    asm volatile("mbarrier.init.shared.b64 [%0], %1;" :: "r"(addr), "r"(count) : "memory");
}
__device__ __forceinline__ void mbar_expect_tx(uint32_t addr, uint32_t bytes) {
    asm volatile("mbarrier.arrive.expect_tx.shared.b64 _, [%0], %1;"
                 :: "r"(addr), "r"(bytes) : "memory");
}
__device__ __forceinline__ void mbar_wait(uint32_t addr, uint32_t parity) {
    asm volatile(
        "{\n\t"
        ".reg .pred P1;\n\t"
        "LAB_WAIT%=:\n\t"
        "mbarrier.try_wait.parity.acquire.cta.shared::cta.b64 P1, [%0], %1, 0x989680;\n\t"
        "@P1 bra LAB_DONE%=;\n\t"
        "bra LAB_WAIT%=;\n\t"
        "LAB_DONE%=:\n\t"
        "}"
        :: "r"(addr), "r"(parity) : "memory");
}
__device__ __forceinline__ void bulk_g2s(uint32_t dst, const float* src,
                                         uint32_t bytes, uint32_t mbar) {
    asm volatile(
        "cp.async.bulk.shared::cluster.global.mbarrier::complete_tx::bytes [%0], [%1], %2, [%3];"
        :: "r"(dst), "l"(src), "r"(bytes), "r"(mbar) : "memory");
}
__device__ __forceinline__ void fence_proxy_async_cta() {
    asm volatile("fence.proxy.async.shared::cta;" ::: "memory");
}

__device__ __forceinline__ float sigf(float x) {
    return 1.0f / (1.0f + __expf(-x));
}
__device__ __forceinline__ float tanh_fast(float x) {
    // tanh(x) = 1 - 2/(1+exp(2x)); NaN-free for +/-inf exp overflow
    return 1.0f - 2.0f / (1.0f + __expf(2.0f * x));
}

// release/acquire software grid barrier (all NCTA CTAs resident: 1 CTA/SM)
__device__ __forceinline__ void grid_barrier() {
    __syncthreads();
    if (threadIdx.x == 0) {
        __threadfence();                       // release CTA's prior writes
        unsigned old = g_bar_gen;
        if (atomicAdd(&g_bar_cnt, 1u) == NCTA - 1u) {
            g_bar_cnt = 0;
            __threadfence();
            g_bar_gen = old + 1u;
        } else {
            while (g_bar_gen == old) { }
        }
        __threadfence();                       // acquire
    }
    __syncthreads();
}

// ---------------------------------------------------------------------------
// Init kernel: reset barrier state, transpose h0 [b][j] -> g_h[0] [j][b]
// ---------------------------------------------------------------------------
__global__ void init_state(const float* __restrict__ h0) {
    int i = blockIdx.x * blockDim.x + threadIdx.x;
    if (i == 0) { g_bar_cnt = 0; g_bar_gen = 0; }
    if (i < HH * BB) {
        int j = i >> 6, b = i & 63;
        g_h[0][i] = h0[b * HH + j];
    }
}

// ---------------------------------------------------------------------------
// Phase A: x_proj[t][g][b] = sum_i input[t][b][i]*W_ih[g][i] + b_ih[g]+b_hh[g]
// Classic 128x128x8 register-tiled SGEMM; M = g (2048), N = t*64+b (32768)
// ---------------------------------------------------------------------------
__global__ void __launch_bounds__(256, 2)
xproj_gemm(const float* __restrict__ input,
           const float* __restrict__ W_ih,
           const float* __restrict__ b_ih,
           const float* __restrict__ b_hh)
{
    __shared__ float As[8][128];
    __shared__ float Bs[8][128];

    const int tid    = threadIdx.x;
    const int gBase  = blockIdx.y * 128;
    const int tbBase = blockIdx.x * 128;
    const int tx = tid & 15, ty = tid >> 4;
    const int lr = tid >> 1;          // 0..127 tile row
    const int lk = (tid & 1) * 4;     // k sub-offset

    float acc[8][8];
    #pragma unroll
    for (int i = 0; i < 8; ++i)
        #pragma unroll
        for (int j = 0; j < 8; ++j) acc[i][j] = 0.0f;

    const float* aptr = W_ih  + (size_t)(gBase  + lr) * II + lk;
    const float* bptr = input + (size_t)(tbBase + lr) * II + lk;

    for (int k0 = 0; k0 < II; k0 += 8) {
        float4 av = *(const float4*)(aptr + k0);
        float4 bv = *(const float4*)(bptr + k0);
        __syncthreads();
        As[lk + 0][lr] = av.x; As[lk + 1][lr] = av.y;
        As[lk + 2][lr] = av.z; As[lk + 3][lr] = av.w;
        Bs[lk + 0][lr] = bv.x; Bs[lk + 1][lr] = bv.y;
        Bs[lk + 2][lr] = bv.z; Bs[lk + 3][lr] = bv.w;
        __syncthreads();
        #pragma unroll
        for (int kk = 0; kk < 8; ++kk) {
            float a[8], bq[8];
            *(float4*)&a[0]  = *(const float4*)&As[kk][ty * 8];
            *(float4*)&a[4]  = *(const float4*)&As[kk][ty * 8 + 4];
            *(float4*)&bq[0] = *(const float4*)&Bs[kk][tx * 8];
            *(float4*)&bq[4] = *(const float4*)&Bs[kk][tx * 8 + 4];
            #pragma unroll
            for (int i = 0; i < 8; ++i)
                #pragma unroll
                for (int j = 0; j < 8; ++j)
                    acc[i][j] += a[i] * bq[j];
        }
    }

    // epilogue: tb0 is 8-aligned so all 8 j's share one t; b runs contiguous
    const int tb0 = tbBase + tx * 8;
    const int t  = tb0 >> 6;
    const int b0 = tb0 & 63;
    float* dstbase = g_xp + (size_t)t * (G4 * BB) + b0;
    #pragma unroll
    for (int i = 0; i < 8; ++i) {
        int g = gBase + ty * 8 + i;
        float bias = b_ih[g] + b_hh[g];
        float4 v0 = make_float4(acc[i][0] + bias, acc[i][1] + bias,
                                acc[i][2] + bias, acc[i][3] + bias);
        float4 v1 = make_float4(acc[i][4] + bias, acc[i][5] + bias,
                                acc[i][6] + bias, acc[i][7] + bias);
        float* dst = dstbase + (size_t)g * 64;
        *(float4*)dst       = v0;
        *(float4*)(dst + 4) = v1;
    }
}

// ---------------------------------------------------------------------------
// Phase B: persistent reverse recurrence.
// CTA k owns h-indices j in [4k,4k+4): 16 gate rows, W slice + c state local.
// h broadcast each step via 4x 32KB cp.async.bulk chunks (pipelined).
// Shared layout: hs[512][64] (128KB) | ws[16][512] (32KB) | gsh[16][64] (4KB) | 4 mbarriers
// ---------------------------------------------------------------------------
#define SM_HS   0
#define SM_WS   131072
#define SM_GSH  (131072 + 32768)
#define SM_MBAR (131072 + 32768 + 4096)
#define SM_TOT  (SM_MBAR + 64)

__global__ void __launch_bounds__(256, 1)
lstm_recurrent(const float* __restrict__ W_hh,
               const float* __restrict__ c0,
               float* __restrict__ out)
{
    extern __shared__ char smem[];
    float* hs  = (float*)(smem + SM_HS);    // [k][b]
    float* ws  = (float*)(smem + SM_WS);    // [16 local gate rows][512]
    float* gsh = (float*)(smem + SM_GSH);   // [16][64]
    const uint32_t hs_u32  = smem_u32(smem + SM_HS);
    const uint32_t mbar0   = smem_u32(smem + SM_MBAR);

    const int tid   = threadIdx.x;
    const int cta   = blockIdx.x;
    const int jbase = cta * 4;

    // load W_hh slice: local row r = q*4+jj  <->  global row q*512 + jbase + jj
    {
        const float4* whh4 = (const float4*)W_hh;
        float4* ws4w = (float4*)ws;
        for (int idx = tid; idx < 16 * 128; idx += 256) {
            int r = idx >> 7, kq = idx & 127;
            int q = r >> 2, jj = r & 3;
            int grow = (q << 9) + jbase + jj;
            ws4w[idx] = whh4[(size_t)grow * 128 + kq];
        }
    }

    // update-role mapping + c state (lives in a register for all 512 steps)
    const int b_u = tid & 63, jj_u = tid >> 6;
    float c_reg = c0[b_u * HH + jbase + jj_u];

    if (tid == 0) {
        #pragma unroll
        for (int i = 0; i < 4; ++i) mbar_init(mbar0 + 8 * i, 1);
    }
    fence_proxy_async_cta();
    __syncthreads();

    // gemm-role mapping: q = gate type, b = batch
    const int b  = tid & 63;
    const int q  = tid >> 6;
    const int r0 = q * 4;
    const float4* ws4 = (const float4*)ws;

    for (int s = 0; s < TT; ++s) {
        const int t   = TT - 1 - s;
        const int cur = s & 1;
        const uint32_t phase = (uint32_t)(s & 1);

        // stage h (current buffer) into shared: 4 pipelined 32KB bulk copies
        if (tid == 0) {
            fence_proxy_async_cta();
            const float* src = g_h[cur];
            #pragma unroll
            for (int ch = 0; ch < 4; ++ch) {
                mbar_expect_tx(mbar0 + 8 * ch, 32768u);
                bulk_g2s(hs_u32 + (uint32_t)ch * 32768u, src + ch * 8192,
                         32768u, mbar0 + 8 * ch);
            }
        }

        // accumulators seeded with x_proj (global LDG overlaps the copy)
        const float* xpt = g_xp + (size_t)t * (G4 * BB)
                         + (size_t)((q << 9) + jbase) * 64 + b;
        float a0 = xpt[0];
        float a1 = xpt[64];
        float a2 = xpt[128];
        float a3 = xpt[192];

        #pragma unroll 1
        for (int ch = 0; ch < 4; ++ch) {
            mbar_wait(mbar0 + 8 * ch, phase);
            const float* hsc = hs + ch * (128 * 64) + b;
            #pragma unroll 4
            for (int kq = 0; kq < 32; ++kq) {
                float h0v = hsc[(kq * 4 + 0) * 64];
                float h1v = hsc[(kq * 4 + 1) * 64];
                float h2v = hsc[(kq * 4 + 2) * 64];
                float h3v = hsc[(kq * 4 + 3) * 64];
                int wq = ch * 32 + kq;
                float4 w0 = ws4[(r0 + 0) * 128 + wq];
                float4 w1 = ws4[(r0 + 1) * 128 + wq];
                float4 w2 = ws4[(r0 + 2) * 128 + wq];
                float4 w3 = ws4[(r0 + 3) * 128 + wq];
                a0 += w0.x * h0v; a1 += w1.x * h0v; a2 += w2.x * h0v; a3 += w3.x * h0v;
                a0 += w0.y * h1v; a1 += w1.y * h1v; a2 += w2.y * h1v; a3 += w3.y * h1v;
                a0 += w0.z * h2v; a1 += w1.z * h2v; a2 += w2.z * h2v; a3 += w3.z * h2v;
                a0 += w0.w * h3v; a1 += w1.w * h3v; a2 += w2.w * h3v; a3 += w3.w * h3v;
            }
        }

        gsh[(r0 + 0) * 64 + b] = a0;
        gsh[(r0 + 1) * 64 + b] = a1;
        gsh[(r0 + 2) * 64 + b] = a2;
        gsh[(r0 + 3) * 64 + b] = a3;
        __syncthreads();

        // elementwise LSTM cell update (thread owns (b_u, j = jbase+jj_u))
        float gi = gsh[( 0 + jj_u) * 64 + b_u];
        float gf = gsh[( 4 + jj_u) * 64 + b_u];
        float gg = gsh[( 8 + jj_u) * 64 + b_u];
        float go = gsh[(12 + jj_u) * 64 + b_u];

        float ig = sigf(gi), fg = sigf(gf), og = sigf(go);
        c_reg = fg * c_reg + ig * tanh_fast(gg);
        float hn = og * tanh_fast(c_reg);

        const int jg = jbase + jj_u;
        g_h[cur ^ 1][jg * 64 + b_u] = hn;
        out[(size_t)t * (BB * HH) + (size_t)b_u * HH + jg] = hn;
        if (s == TT - 1) {
            out[(size_t)TT * (BB * HH) + (size_t)b_u * HH + jg]           = hn;  // h_f
            out[(size_t)TT * (BB * HH) + BB * HH + (size_t)b_u * HH + jg] = c_reg; // c_f
        }

        grid_barrier();   // release h writes to all CTAs; also fences smem reuse
    }
}

// ---------------------------------------------------------------------------
// Launch
// ---------------------------------------------------------------------------
extern "C" void kernel_launch(void* const* d_in, const int* in_sizes, int n_in,
                              void* d_out, int out_size)
{
    (void)in_sizes; (void)n_in; (void)out_size;
    const float* input = (const float*)d_in[0];
    const float* h0    = (const float*)d_in[1];
    const float* c0    = (const float*)d_in[2];
    const float* W_ih  = (const float*)d_in[3];
    const float* W_hh  = (const float*)d_in[4];
    const float* b_ih  = (const float*)d_in[5];
    const float* b_hh  = (const float*)d_in[6];
    float* out = (float*)d_out;

    cudaFuncSetAttribute(lstm_recurrent,
                         cudaFuncAttributeMaxDynamicSharedMemorySize, SM_TOT);

    init_state<<<128, 256>>>(h0);

    dim3 ggrid(256, 16);   // N tiles (tb) x M tiles (g)
    xproj_gemm<<<ggrid, 256>>>(input, W_ih, b_ih, b_hh);

    lstm_recurrent<<<NCTA, 256, SM_TOT>>>(W_hh, c0, out);
}

// round 6
// speedup vs baseline: 1.1691x; 1.1691x over previous
#include <cuda_runtime.h>
#include <cuda_bf16.h>
#include <cstdint>

// Problem dims
#define TT   512
#define BB   64
#define II   512
#define HH   512
#define G4   2048          // 4*H gate rows
#define NCTA 128           // persistent CTAs for recurrence

// Phase A GEMM tiling (mma.sync bf16, base-target PTX only — NO tcgen05)
#define KCH     32                  // k elems per chunk
#define NCHK    (II / KCH)          // 16 chunks
#define SROW    40                  // padded smem row (elems): 80B, conflict-free
#define TILEB   (128 * SROW * 2)    // 10240 B per matrix tile
#define STAGEB  (4 * TILEB)         // A_hi|A_lo|B_hi|B_lo = 40960 B
#define SMEM_A_TOT (2 * STAGEB)     // 81920 B double-buffered

// ---------------------------------------------------------------------------
// Global scratch (static __device__ arrays — no allocation allowed)
// ---------------------------------------------------------------------------
__device__ float g_xp[(size_t)TT * G4 * BB];        // x_proj [t][g][b]
__device__ float g_h[2][HH * BB];                   // h double buffer [j][b]
__device__ __nv_bfloat16 g_in_hi[(size_t)TT * BB * II];
__device__ __nv_bfloat16 g_in_lo[(size_t)TT * BB * II];
__device__ __nv_bfloat16 g_w_hi[(size_t)G4 * II];
__device__ __nv_bfloat16 g_w_lo[(size_t)G4 * II];
__device__ unsigned int          g_bar_cnt;
__device__ volatile unsigned int g_bar_gen;

// ---------------------------------------------------------------------------
// PTX helpers (all base-target features: sm_80/sm_90, no 'a' suffix required)
// ---------------------------------------------------------------------------
__device__ __forceinline__ uint32_t smem_u32(const void* p) {
    uint32_t a;
    asm("{ .reg .u64 t; cvta.to.shared.u64 t, %1; cvt.u32.u64 %0, t; }"
        : "=r"(a) : "l"(p));
    return a;
}
__device__ __forceinline__ void mbar_init(uint32_t addr, uint32_t count) {
    asm volatile("mbarrier.init.shared.b64 [%0], %1;" :: "r"(addr), "r"(count) : "memory");
}
__device__ __forceinline__ void mbar_expect_tx(uint32_t addr, uint32_t bytes) {
    asm volatile("mbarrier.arrive.expect_tx.shared.b64 _, [%0], %1;"
                 :: "r"(addr), "r"(bytes) : "memory");
}
__device__ __forceinline__ void mbar_wait(uint32_t addr, uint32_t parity) {
    asm volatile(
        "{\n\t"
        ".reg .pred P1;\n\t"
        "LAB_WAIT%=:\n\t"
        "mbarrier.try_wait.parity.acquire.cta.shared::cta.b64 P1, [%0], %1, 0x989680;\n\t"
        "@P1 bra LAB_DONE%=;\n\t"
        "bra LAB_WAIT%=;\n\t"
        "LAB_DONE%=:\n\t"
        "}"
        :: "r"(addr), "r"(parity) : "memory");
}
__device__ __forceinline__ void bulk_g2s(uint32_t dst, const float* src,
                                         uint32_t bytes, uint32_t mbar) {
    asm volatile(
        "cp.async.bulk.shared::cluster.global.mbarrier::complete_tx::bytes [%0], [%1], %2, [%3];"
        :: "r"(dst), "l"(src), "r"(bytes), "r"(mbar) : "memory");
}
__device__ __forceinline__ void fence_proxy_async_cta() {
    asm volatile("fence.proxy.async.shared::cta;" ::: "memory");
}
__device__ __forceinline__ void cpasync16(uint32_t dst, const void* src) {
    asm volatile("cp.async.cg.shared.global [%0], [%1], 16;"
                 :: "r"(dst), "l"(src) : "memory");
}
__device__ __forceinline__ void cp_commit() {
    asm volatile("cp.async.commit_group;" ::: "memory");
}
__device__ __forceinline__ void ldsm4(uint32_t* r, uint32_t addr) {
    asm volatile("ldmatrix.sync.aligned.m8n8.x4.shared.b16 {%0,%1,%2,%3}, [%4];"
                 : "=r"(r[0]), "=r"(r[1]), "=r"(r[2]), "=r"(r[3]) : "r"(addr));
}
__device__ __forceinline__ void mma16816(float* d, const uint32_t* a, const uint32_t* b) {
    asm volatile(
        "mma.sync.aligned.m16n8k16.row.col.f32.bf16.bf16.f32 "
        "{%0,%1,%2,%3}, {%4,%5,%6,%7}, {%8,%9}, {%0,%1,%2,%3};"
        : "+f"(d[0]), "+f"(d[1]), "+f"(d[2]), "+f"(d[3])
        : "r"(a[0]), "r"(a[1]), "r"(a[2]), "r"(a[3]), "r"(b[0]), "r"(b[1]));
}

__device__ __forceinline__ float sigf(float x) { return 1.0f / (1.0f + __expf(-x)); }
__device__ __forceinline__ float tanh_fast(float x) {
    return 1.0f - 2.0f / (1.0f + __expf(2.0f * x));
}

// release/acquire software grid barrier (all NCTA CTAs resident)
__device__ __forceinline__ void grid_barrier() {
    __syncthreads();
    if (threadIdx.x == 0) {
        __threadfence();
        unsigned old = g_bar_gen;
        if (atomicAdd(&g_bar_cnt, 1u) == NCTA - 1u) {
            g_bar_cnt = 0;
            __threadfence();
            g_bar_gen = old + 1u;
        } else {
            while (g_bar_gen == old) { }
        }
        __threadfence();
    }
    __syncthreads();
}

// ---------------------------------------------------------------------------
// Init: barrier reset + h0 transpose
// ---------------------------------------------------------------------------
__global__ void init_state(const float* __restrict__ h0) {
    int i = blockIdx.x * blockDim.x + threadIdx.x;
    if (i == 0) { g_bar_cnt = 0; g_bar_gen = 0; }
    if (i < HH * BB) {
        int j = i >> 6, b = i & 63;
        g_h[0][i] = h0[b * HH + j];
    }
}

// ---------------------------------------------------------------------------
// Split fp32 -> bf16 hi/lo for input and W_ih
// ---------------------------------------------------------------------------
__global__ void convert_split(const float* __restrict__ input,
                              const float* __restrict__ W_ih) {
    const size_t n_in = (size_t)TT * BB * II;
    const size_t n_w  = (size_t)G4 * II;
    size_t stride = (size_t)gridDim.x * blockDim.x;
    for (size_t i = blockIdx.x * (size_t)blockDim.x + threadIdx.x; i < n_in; i += stride) {
        float x = input[i];
        __nv_bfloat16 h = __float2bfloat16(x);
        g_in_hi[i] = h;
        g_in_lo[i] = __float2bfloat16(x - __bfloat162float(h));
    }
    for (size_t i = blockIdx.x * (size_t)blockDim.x + threadIdx.x; i < n_w; i += stride) {
        float x = W_ih[i];
        __nv_bfloat16 h = __float2bfloat16(x);
        g_w_hi[i] = h;
        g_w_lo[i] = __float2bfloat16(x - __bfloat162float(h));
    }
}

// ---------------------------------------------------------------------------
// Phase A: x_proj via mma.sync bf16 split GEMM (3 passes: hh + hl + lh).
// D[g, tb] = sum_k W[g,k] * X[tb,k].
// CTA tile 128x128, K-chunk 32, cp.async double buffer, 8 warps (64x32 each).
// ---------------------------------------------------------------------------
__device__ __forceinline__ void load_chunk_a(int c, int stage, int mbase, int nbase,
                                             uint32_t sbase) {
    const int tid = threadIdx.x;
    const uint32_t st = sbase + (uint32_t)stage * STAGEB;
    #pragma unroll
    for (int it = 0; it < 8; ++it) {
        int i = tid + it * 256;
        int which = i >> 10;            // 0 = A(W), 1 = B(X)
        int rem   = i & 1023;
        int hl    = (rem >> 9) & 1;     // 0 = hi, 1 = lo
        int r     = (rem >> 2) & 127;
        int cc    = rem & 3;            // 8-elem (16B) column chunk
        const __nv_bfloat16* gsrc =
            which ? (hl ? g_in_lo : g_in_hi) : (hl ? g_w_lo : g_w_hi);
        int grow = which ? (nbase + r) : (mbase + r);
        const void* src = gsrc + (size_t)grow * II + c * KCH + cc * 8;
        uint32_t dst = st + (uint32_t)which * (2 * TILEB) + (uint32_t)hl * TILEB
                     + (uint32_t)(r * (SROW * 2) + cc * 16);
        cpasync16(dst, src);
    }
    cp_commit();
}

__global__ void __launch_bounds__(256, 2)
xproj_mma(const float* __restrict__ b_ih, const float* __restrict__ b_hh) {
    extern __shared__ char dsm[];
    const uint32_t sbase = smem_u32(dsm);

    const int tid  = threadIdx.x;
    const int wid  = tid >> 5;
    const int lane = tid & 31;
    const int mbase = blockIdx.x * 128;   // g
    const int nbase = blockIdx.y * 128;   // tb
    const int wm = (wid >> 2) * 64;       // warp m offset
    const int wn = (wid & 3) * 32;        // warp n offset

    // ldmatrix per-lane byte offsets (within one matrix tile), k=0
    uint32_t aoff[4], boff[2];
    {
        int l15 = lane & 15, lhi = lane >> 4;
        #pragma unroll
        for (int f = 0; f < 4; ++f)
            aoff[f] = (uint32_t)(((wm + f * 16 + l15) * SROW + lhi * 8) * 2);
        int sub = lane & 7, grp = lane >> 3;
        #pragma unroll
        for (int p = 0; p < 2; ++p)
            boff[p] = (uint32_t)(((wn + p * 16 + (grp >> 1) * 8 + sub) * SROW
                                  + (grp & 1) * 8) * 2);
    }

    float acc[4][4][4];
    #pragma unroll
    for (int f = 0; f < 4; ++f)
        #pragma unroll
        for (int n = 0; n < 4; ++n)
            #pragma unroll
            for (int e = 0; e < 4; ++e) acc[f][n][e] = 0.0f;

    load_chunk_a(0, 0, mbase, nbase, sbase);
    load_chunk_a(1, 1, mbase, nbase, sbase);

    for (int c = 0; c < NCHK; ++c) {
        if (c < NCHK - 1) asm volatile("cp.async.wait_group 1;" ::: "memory");
        else              asm volatile("cp.async.wait_group 0;" ::: "memory");
        __syncthreads();

        const uint32_t st = sbase + (uint32_t)(c & 1) * STAGEB;
        const uint32_t Ah = st, Al = st + TILEB, Bh = st + 2 * TILEB, Bl = st + 3 * TILEB;

        #pragma unroll
        for (int step = 0; step < 2; ++step) {
            const uint32_t ko = (uint32_t)step * 32;   // 16 elems * 2B
            uint32_t ah[16], bh[8], bl[8];
            #pragma unroll
            for (int f = 0; f < 4; ++f) ldsm4(&ah[f * 4], Ah + aoff[f] + ko);
            #pragma unroll
            for (int p = 0; p < 2; ++p) {
                ldsm4(&bh[p * 4], Bh + boff[p] + ko);
                ldsm4(&bl[p * 4], Bl + boff[p] + ko);
            }
            #pragma unroll
            for (int f = 0; f < 4; ++f)
                #pragma unroll
                for (int n = 0; n < 4; ++n) {
                    mma16816(acc[f][n], &ah[f * 4], &bh[n * 2]);
                    mma16816(acc[f][n], &ah[f * 4], &bl[n * 2]);
                }
            uint32_t al[16];
            #pragma unroll
            for (int f = 0; f < 4; ++f) ldsm4(&al[f * 4], Al + aoff[f] + ko);
            #pragma unroll
            for (int f = 0; f < 4; ++f)
                #pragma unroll
                for (int n = 0; n < 4; ++n)
                    mma16816(acc[f][n], &al[f * 4], &bh[n * 2]);
        }
        __syncthreads();
        if (c + 2 < NCHK) load_chunk_a(c + 2, (c & 1), mbase, nbase, sbase);
    }

    // Epilogue: accum layout m16n8: rows lane/4 (+8), cols (lane%4)*2 (+1)
    const int rrow = lane >> 2;
    const int ncol = (lane & 3) * 2;
    #pragma unroll
    for (int f = 0; f < 4; ++f) {
        const int g0 = mbase + wm + f * 16 + rrow;
        const float bias0 = b_ih[g0] + b_hh[g0];
        const float bias1 = b_ih[g0 + 8] + b_hh[g0 + 8];
        #pragma unroll
        for (int n = 0; n < 4; ++n) {
            const int tb = nbase + wn + n * 8 + ncol;
            const int t  = tb >> 6;
            const int b  = tb & 63;
            float* base = g_xp + (size_t)t * (G4 * BB) + b;
            float2 v0 = make_float2(acc[f][n][0] + bias0, acc[f][n][1] + bias0);
            float2 v1 = make_float2(acc[f][n][2] + bias1, acc[f][n][3] + bias1);
            *(float2*)(base + (size_t)g0 * 64)       = v0;
            *(float2*)(base + (size_t)(g0 + 8) * 64) = v1;
        }
    }
}

// ---------------------------------------------------------------------------
// Phase B: persistent reverse recurrence (unchanged from R2 — passing baseline)
// ---------------------------------------------------------------------------
#define SM_HS   0
#define SM_WS   131072
#define SM_GSH  (131072 + 32768)
#define SM_MBAR (131072 + 32768 + 4096)
#define SM_TOT  (SM_MBAR + 64)

__global__ void __launch_bounds__(256, 1)
lstm_recurrent(const float* __restrict__ W_hh,
               const float* __restrict__ c0,
               float* __restrict__ out)
{
    extern __shared__ char smem[];
    float* hs  = (float*)(smem + SM_HS);
    float* ws  = (float*)(smem + SM_WS);
    float* gsh = (float*)(smem + SM_GSH);
    const uint32_t hs_u32 = smem_u32(smem + SM_HS);
    const uint32_t mbar0  = smem_u32(smem + SM_MBAR);

    const int tid   = threadIdx.x;
    const int cta   = blockIdx.x;
    const int jbase = cta * 4;

    {
        const float4* whh4 = (const float4*)W_hh;
        float4* ws4w = (float4*)ws;
        for (int idx = tid; idx < 16 * 128; idx += 256) {
            int r = idx >> 7, kq = idx & 127;
            int q = r >> 2, jj = r & 3;
            int grow = (q << 9) + jbase + jj;
            ws4w[idx] = whh4[(size_t)grow * 128 + kq];
        }
    }

    const int b_u = tid & 63, jj_u = tid >> 6;
    float c_reg = c0[b_u * HH + jbase + jj_u];

    if (tid == 0) {
        #pragma unroll
        for (int i = 0; i < 4; ++i) mbar_init(mbar0 + 8 * i, 1);
    }
    fence_proxy_async_cta();
    __syncthreads();

    const int b  = tid & 63;
    const int q  = tid >> 6;
    const int r0 = q * 4;
    const float4* ws4 = (const float4*)ws;

    for (int s = 0; s < TT; ++s) {
        const int t   = TT - 1 - s;
        const int cur = s & 1;
        const uint32_t phase = (uint32_t)(s & 1);

        if (tid == 0) {
            fence_proxy_async_cta();
            const float* src = g_h[cur];
            #pragma unroll
            for (int ch = 0; ch < 4; ++ch) {
                mbar_expect_tx(mbar0 + 8 * ch, 32768u);
                bulk_g2s(hs_u32 + (uint32_t)ch * 32768u, src + ch * 8192,
                         32768u, mbar0 + 8 * ch);
            }
        }

        const float* xpt = g_xp + (size_t)t * (G4 * BB)
                         + (size_t)((q << 9) + jbase) * 64 + b;
        float a0 = xpt[0];
        float a1 = xpt[64];
        float a2 = xpt[128];
        float a3 = xpt[192];

        #pragma unroll 1
        for (int ch = 0; ch < 4; ++ch) {
            mbar_wait(mbar0 + 8 * ch, phase);
            const float* hsc = hs + ch * (128 * 64) + b;
            #pragma unroll 4
            for (int kq = 0; kq < 32; ++kq) {
                float h0v = hsc[(kq * 4 + 0) * 64];
                float h1v = hsc[(kq * 4 + 1) * 64];
                float h2v = hsc[(kq * 4 + 2) * 64];
                float h3v = hsc[(kq * 4 + 3) * 64];
                int wq = ch * 32 + kq;
                float4 w0 = ws4[(r0 + 0) * 128 + wq];
                float4 w1 = ws4[(r0 + 1) * 128 + wq];
                float4 w2 = ws4[(r0 + 2) * 128 + wq];
                float4 w3 = ws4[(r0 + 3) * 128 + wq];
                a0 += w0.x * h0v; a1 += w1.x * h0v; a2 += w2.x * h0v; a3 += w3.x * h0v;
                a0 += w0.y * h1v; a1 += w1.y * h1v; a2 += w2.y * h1v; a3 += w3.y * h1v;
                a0 += w0.z * h2v; a1 += w1.z * h2v; a2 += w2.z * h2v; a3 += w3.z * h2v;
                a0 += w0.w * h3v; a1 += w1.w * h3v; a2 += w2.w * h3v; a3 += w3.w * h3v;
            }
        }

        gsh[(r0 + 0) * 64 + b] = a0;
        gsh[(r0 + 1) * 64 + b] = a1;
        gsh[(r0 + 2) * 64 + b] = a2;
        gsh[(r0 + 3) * 64 + b] = a3;
        __syncthreads();

        float gi = gsh[( 0 + jj_u) * 64 + b_u];
        float gf = gsh[( 4 + jj_u) * 64 + b_u];
        float gg = gsh[( 8 + jj_u) * 64 + b_u];
        float go = gsh[(12 + jj_u) * 64 + b_u];

        float ig = sigf(gi), fg = sigf(gf), og = sigf(go);
        c_reg = fg * c_reg + ig * tanh_fast(gg);
        float hn = og * tanh_fast(c_reg);

        const int jg = jbase + jj_u;
        g_h[cur ^ 1][jg * 64 + b_u] = hn;
        out[(size_t)t * (BB * HH) + (size_t)b_u * HH + jg] = hn;
        if (s == TT - 1) {
            out[(size_t)TT * (BB * HH) + (size_t)b_u * HH + jg]             = hn;
            out[(size_t)TT * (BB * HH) + BB * HH + (size_t)b_u * HH + jg]   = c_reg;
        }

        grid_barrier();
    }
}

// ---------------------------------------------------------------------------
// Launch
// ---------------------------------------------------------------------------
extern "C" void kernel_launch(void* const* d_in, const int* in_sizes, int n_in,
                              void* d_out, int out_size)
{
    (void)in_sizes; (void)n_in; (void)out_size;
    const float* input = (const float*)d_in[0];
    const float* h0    = (const float*)d_in[1];
    const float* c0    = (const float*)d_in[2];
    const float* W_ih  = (const float*)d_in[3];
    const float* W_hh  = (const float*)d_in[4];
    const float* b_ih  = (const float*)d_in[5];
    const float* b_hh  = (const float*)d_in[6];
    float* out = (float*)d_out;

    cudaFuncSetAttribute(lstm_recurrent,
                         cudaFuncAttributeMaxDynamicSharedMemorySize, SM_TOT);
    cudaFuncSetAttribute(xproj_mma,
                         cudaFuncAttributeMaxDynamicSharedMemorySize, SMEM_A_TOT);

    init_state<<<128, 256>>>(h0);
    convert_split<<<1024, 256>>>(input, W_ih);

    dim3 ggrid(G4 / 128, (TT * BB) / 128);   // (16, 256); m fast -> B-tile L2 reuse
    xproj_mma<<<ggrid, 256, SMEM_A_TOT>>>(b_ih, b_hh);

    lstm_recurrent<<<NCTA, 256, SM_TOT>>>(W_hh, c0, out);
}